// round 3
// baseline (speedup 1.0000x reference)
#include <cuda_runtime.h>
#include <cstdint>

namespace {
constexpr int Bc = 8, Hc = 16, Sc = 1024, Dc = 64;
constexpr int BH = Bc * Hc;
constexpr int TQ = 16;            // q rows per CTA
constexpr int NT = 256;           // 8 warps
constexpr int KT = 64;            // k tile
constexpr int SQ_P = 68;          // Q pitch (conflict-free frag LDS)
constexpr int SS_P = 1028;        // score pitch (conflict-free frag LDS)
constexpr int SMEM_FLOATS = TQ * SS_P + TQ * SQ_P;   // 17536 fl = 70144 B
constexpr size_t ATTN_OFF = (size_t)BH * Sc * Dc;    // out first, then attn
constexpr int PP = 72;            // partial-reduction row pitch
}

__device__ __forceinline__ float to_tf32(float x) {
    uint32_t u;
    asm("cvt.rna.tf32.f32 %0, %1;" : "=r"(u) : "f"(x));
    return __uint_as_float(u);
}

__device__ __forceinline__ void mma8(float c[4],
                                     float a0, float a1, float a2, float a3,
                                     float b0, float b1) {
    asm volatile(
        "mma.sync.aligned.m16n8k8.row.col.f32.tf32.tf32.f32 "
        "{%0,%1,%2,%3}, {%4,%5,%6,%7}, {%8,%9}, {%0,%1,%2,%3};\n"
        : "+f"(c[0]), "+f"(c[1]), "+f"(c[2]), "+f"(c[3])
        : "r"(__float_as_uint(a0)), "r"(__float_as_uint(a1)),
          "r"(__float_as_uint(a2)), "r"(__float_as_uint(a3)),
          "r"(__float_as_uint(b0)), "r"(__float_as_uint(b1)));
}

__global__ void __launch_bounds__(NT, 2)
attn_tf32_kernel(const float* __restrict__ Qg_, const float* __restrict__ Kg_,
                 const float* __restrict__ Vg_, const int* __restrict__ Mg_,
                 float* __restrict__ out)
{
    extern __shared__ float sm[];
    float* sS = sm;                       // [TQ][SS_P]; later: reduction buffer
    float* sQ = sS + TQ * SS_P;           // [TQ][SQ_P]

    const int qt   = blockIdx.x;          // 0..63
    const int bh   = blockIdx.y;          // 0..127
    const int b    = bh >> 4;
    const int tid  = threadIdx.x;
    const int warp = tid >> 5;            // 0..7
    const int lane = tid & 31;
    const int gid  = lane >> 2;           // 0..7
    const int tig  = lane & 3;            // 0..3
    const int w8   = warp << 3;

    const float* Qg = Qg_ + ((size_t)bh * Sc + (size_t)qt * TQ) * Dc;
    const float* Kg = Kg_ + (size_t)bh * Sc * Dc;
    const float* Vg = Vg_ + (size_t)bh * Sc * Dc;
    float* outO = out + ((size_t)bh * Sc + (size_t)qt * TQ) * Dc;
    float* outA = out + ATTN_OFF + ((size_t)bh * Sc + (size_t)qt * TQ) * Sc;
    const int* Mg = Mg_ + ((size_t)b * Sc + (size_t)qt * TQ) * Sc;

    // ---------------- Q tile -> smem (scaled by 1/8, tf32) -------------------
    {
        int i = tid;                       // 256 float4s, one per thread
        int row = i >> 4, c4 = i & 15;
        float4 v = reinterpret_cast<const float4*>(Qg)[i];
        float* dst = sQ + row * SQ_P + c4 * 4;
        dst[0] = to_tf32(v.x * 0.125f);
        dst[1] = to_tf32(v.y * 0.125f);
        dst[2] = to_tf32(v.z * 0.125f);
        dst[3] = to_tf32(v.w * 0.125f);
    }
    __syncthreads();

    // A fragments (Q), reused across all 16 K tiles
    float aq[8][4];
#pragma unroll
    for (int ks = 0; ks < 8; ks++) {
        const float* p = sQ + gid * SQ_P + ks * 8 + tig;
        aq[ks][0] = p[0];
        aq[ks][1] = p[8 * SQ_P];
        aq[ks][2] = p[4];
        aq[ks][3] = p[8 * SQ_P + 4];
    }

    // ---------------- GEMM1: B fragments straight from gmem ------------------
    // score col (within tile) block = w8; K row = kt*64 + w8 + gid
    {
        const float* pk = Kg + (size_t)(w8 + gid) * Dc + tig;
        float bk[2][16];
#pragma unroll
        for (int ks = 0; ks < 8; ks++) {
            bk[0][2 * ks]     = to_tf32(pk[ks * 8]);
            bk[0][2 * ks + 1] = to_tf32(pk[ks * 8 + 4]);
        }
        for (int kt = 0; kt < Sc / KT; kt++) {
            int cur = kt & 1;
            if (kt < 15) {
                const float* pn = pk + (size_t)(kt + 1) * KT * Dc;
#pragma unroll
                for (int ks = 0; ks < 8; ks++) {
                    bk[cur ^ 1][2 * ks]     = to_tf32(pn[ks * 8]);
                    bk[cur ^ 1][2 * ks + 1] = to_tf32(pn[ks * 8 + 4]);
                }
            }
            float c[4] = {0.f, 0.f, 0.f, 0.f};
#pragma unroll
            for (int ks = 0; ks < 8; ks++)
                mma8(c, aq[ks][0], aq[ks][1], aq[ks][2], aq[ks][3],
                     bk[cur][2 * ks], bk[cur][2 * ks + 1]);

            int col = kt * KT + w8 + tig * 2;
            float* p  = sS + gid * SS_P + col;
            float* p2 = p + 8 * SS_P;
            p[0]  = c[0]; p[1]  = c[1];
            p2[0] = c[2]; p2[1] = c[3];
        }
    }
    __syncthreads();

    // ---------------- softmax + post-softmax mask + attn write ---------------
#pragma unroll
    for (int rr = 0; rr < 2; rr++) {      // each warp owns 2 rows
        int row = warp * 2 + rr;
        float* srow = sS + row * SS_P;
        float4* srow4 = reinterpret_cast<float4*>(srow);

        float mx = -3.0e38f;
#pragma unroll
        for (int i = 0; i < 8; i++) {
            float4 v = srow4[lane + i * 32];
            mx = fmaxf(mx, fmaxf(fmaxf(v.x, v.y), fmaxf(v.z, v.w)));
        }
#pragma unroll
        for (int o = 16; o > 0; o >>= 1)
            mx = fmaxf(mx, __shfl_xor_sync(0xffffffffu, mx, o));

        float sum = 0.f;
        float4 e[8];
#pragma unroll
        for (int i = 0; i < 8; i++) {
            float4 v = srow4[lane + i * 32];
            v.x = __expf(v.x - mx); v.y = __expf(v.y - mx);
            v.z = __expf(v.z - mx); v.w = __expf(v.w - mx);
            e[i] = v;
            sum += (v.x + v.y) + (v.z + v.w);
        }
#pragma unroll
        for (int o = 16; o > 0; o >>= 1)
            sum += __shfl_xor_sync(0xffffffffu, sum, o);
        float inv = 1.0f / sum;

        const int4* mrow = reinterpret_cast<const int4*>(Mg + (size_t)row * Sc);
        float4* arow = reinterpret_cast<float4*>(outA + (size_t)row * Sc);
#pragma unroll
        for (int i = 0; i < 8; i++) {
            int idx = lane + i * 32;
            int4 m = mrow[idx];
            float4 w;
            w.x = m.x ? e[i].x * inv : -100000.0f;
            w.y = m.y ? e[i].y * inv : -100000.0f;
            w.z = m.z ? e[i].z * inv : -100000.0f;
            w.w = m.w ? e[i].w * inv : -100000.0f;
            __stcs(&arow[idx], w);                 // exact fp32 attn, streaming
            float4 t;                              // tf32 copy for GEMM2
            t.x = to_tf32(w.x); t.y = to_tf32(w.y);
            t.z = to_tf32(w.z); t.w = to_tf32(w.w);
            srow4[idx] = t;
        }
    }
    __syncthreads();

    // ---------------- GEMM2: k-split across warps, V direct from gmem --------
    // Warp owns k-tiles {2*warp, 2*warp+1}; computes full 16x64 partial.
    float c2[8][4];
#pragma unroll
    for (int nb = 0; nb < 8; nb++) {
        c2[nb][0] = 0.f; c2[nb][1] = 0.f; c2[nb][2] = 0.f; c2[nb][3] = 0.f;
    }
    {
        const int wt0 = warp * 2;
        // V element (step, nb, j): Vg[(wt0*64 + step*8 + tig + j*4)*64 + nb*8 + gid]
        const float* pv = Vg + (size_t)wt0 * KT * Dc + (size_t)tig * Dc + gid;
        const float* pa = sS + gid * SS_P + wt0 * KT + tig;

        float bv[2][16];
#pragma unroll
        for (int nb = 0; nb < 8; nb++) {
            bv[0][2 * nb]     = to_tf32(pv[nb * 8]);
            bv[0][2 * nb + 1] = to_tf32(pv[256 + nb * 8]);
        }
        for (int step = 0; step < 16; step++) {
            int cur = step & 1;
            if (step < 15) {
                const float* pn = pv + (size_t)(step + 1) * 8 * Dc;
#pragma unroll
                for (int nb = 0; nb < 8; nb++) {
                    bv[cur ^ 1][2 * nb]     = to_tf32(pn[nb * 8]);
                    bv[cur ^ 1][2 * nb + 1] = to_tf32(pn[256 + nb * 8]);
                }
            }
            const float* ap = pa + step * 8;
            float a0 = ap[0];
            float a1 = ap[8 * SS_P];
            float a2 = ap[4];
            float a3 = ap[8 * SS_P + 4];
#pragma unroll
            for (int nb = 0; nb < 8; nb++)
                mma8(c2[nb], a0, a1, a2, a3,
                     bv[cur][2 * nb], bv[cur][2 * nb + 1]);
        }
    }
    __syncthreads();      // all warps done reading sS attn

    // ---------------- cross-warp reduction of partials (reuse sS) ------------
    {
        float* sP = sS;   // [8 warps][16 rows][PP]
#pragma unroll
        for (int nb = 0; nb < 8; nb++) {
            float2* p0 = reinterpret_cast<float2*>(
                sP + warp * (TQ * PP) + gid * PP + nb * 8 + tig * 2);
            float2* p1 = reinterpret_cast<float2*>(
                sP + warp * (TQ * PP) + (gid + 8) * PP + nb * 8 + tig * 2);
            *p0 = make_float2(c2[nb][0], c2[nb][1]);
            *p1 = make_float2(c2[nb][2], c2[nb][3]);
        }
        __syncthreads();

        int r  = tid >> 4;          // 0..15
        int cc = (tid & 15) * 4;    // 0..60
        float4 acc = make_float4(0.f, 0.f, 0.f, 0.f);
#pragma unroll
        for (int w = 0; w < 8; w++) {
            float4 v = *reinterpret_cast<const float4*>(
                sP + w * (TQ * PP) + r * PP + cc);
            acc.x += v.x; acc.y += v.y; acc.z += v.z; acc.w += v.w;
        }
        *reinterpret_cast<float4*>(outO + r * Dc + cc) = acc;
    }
}

extern "C" void kernel_launch(void* const* d_in, const int* in_sizes, int n_in,
                              void* d_out, int out_size)
{
    (void)in_sizes; (void)n_in; (void)out_size;
    const float* Q = (const float*)d_in[0];
    const float* K = (const float*)d_in[1];
    const float* V = (const float*)d_in[2];
    const int*   M = (const int*)d_in[3];
    float* out = (float*)d_out;

    cudaFuncSetAttribute(attn_tf32_kernel,
                         cudaFuncAttributeMaxDynamicSharedMemorySize,
                         SMEM_FLOATS * (int)sizeof(float));
    dim3 grid(Sc / TQ, BH);
    attn_tf32_kernel<<<grid, NT, SMEM_FLOATS * sizeof(float)>>>(Q, K, V, M, out);
}

// round 4
// speedup vs baseline: 1.0006x; 1.0006x over previous
#include <cuda_runtime.h>
#include <cstdint>

namespace {
constexpr int Bc = 8, Hc = 16, Sc = 1024, Dc = 64;
constexpr int BH = Bc * Hc;
constexpr int TQ = 16;            // q rows per CTA
constexpr int NT = 256;           // 8 warps
constexpr int KT = 64;            // k tile
constexpr int SQ_P = 68;          // Q pitch (conflict-free frag LDS)
constexpr int SS_P = 1028;        // score pitch (conflict-free frag LDS)
constexpr int SMEM_FLOATS = TQ * SS_P + TQ * SQ_P;   // 17536 fl = 70144 B
constexpr size_t ATTN_OFF = (size_t)BH * Sc * Dc;    // out first, then attn
constexpr int PP = 72;            // partial-reduction row pitch
}

__device__ __forceinline__ float to_tf32(float x) {
    uint32_t u;
    asm("cvt.rna.tf32.f32 %0, %1;" : "=r"(u) : "f"(x));
    return __uint_as_float(u);
}

__device__ __forceinline__ void mma8(float c[4],
                                     float a0, float a1, float a2, float a3,
                                     float b0, float b1) {
    asm volatile(
        "mma.sync.aligned.m16n8k8.row.col.f32.tf32.tf32.f32 "
        "{%0,%1,%2,%3}, {%4,%5,%6,%7}, {%8,%9}, {%0,%1,%2,%3};\n"
        : "+f"(c[0]), "+f"(c[1]), "+f"(c[2]), "+f"(c[3])
        : "r"(__float_as_uint(a0)), "r"(__float_as_uint(a1)),
          "r"(__float_as_uint(a2)), "r"(__float_as_uint(a3)),
          "r"(__float_as_uint(b0)), "r"(__float_as_uint(b1)));
}

__global__ void __launch_bounds__(NT, 2)
attn_tf32_kernel(const float* __restrict__ Qg_, const float* __restrict__ Kg_,
                 const float* __restrict__ Vg_, const int* __restrict__ Mg_,
                 float* __restrict__ out)
{
    extern __shared__ float sm[];
    float* sS = sm;                       // [TQ][SS_P]; later: reduction buffer
    float* sQ = sS + TQ * SS_P;           // [TQ][SQ_P]

    const int qt   = blockIdx.x;          // 0..63
    const int bh   = blockIdx.y;          // 0..127
    const int b    = bh >> 4;
    const int tid  = threadIdx.x;
    const int warp = tid >> 5;            // 0..7
    const int lane = tid & 31;
    const int gid  = lane >> 2;           // 0..7
    const int tig  = lane & 3;            // 0..3
    const int w8   = warp << 3;

    const float* Qg = Qg_ + ((size_t)bh * Sc + (size_t)qt * TQ) * Dc;
    const float* Kg = Kg_ + (size_t)bh * Sc * Dc;
    const float* Vg = Vg_ + (size_t)bh * Sc * Dc;
    float* outO = out + ((size_t)bh * Sc + (size_t)qt * TQ) * Dc;
    float* outA = out + ATTN_OFF + ((size_t)bh * Sc + (size_t)qt * TQ) * Sc;
    const int* Mg = Mg_ + ((size_t)b * Sc + (size_t)qt * TQ) * Sc;

    // ---------------- Q tile -> smem (scaled by 1/8, tf32) -------------------
    {
        int i = tid;                       // 256 float4s, one per thread
        int row = i >> 4, c4 = i & 15;
        float4 v = reinterpret_cast<const float4*>(Qg)[i];
        float* dst = sQ + row * SQ_P + c4 * 4;
        dst[0] = to_tf32(v.x * 0.125f);
        dst[1] = to_tf32(v.y * 0.125f);
        dst[2] = to_tf32(v.z * 0.125f);
        dst[3] = to_tf32(v.w * 0.125f);
    }
    __syncthreads();

    // A fragments (Q), reused across all 16 K tiles
    float aq[8][4];
#pragma unroll
    for (int ks = 0; ks < 8; ks++) {
        const float* p = sQ + gid * SQ_P + ks * 8 + tig;
        aq[ks][0] = p[0];
        aq[ks][1] = p[8 * SQ_P];
        aq[ks][2] = p[4];
        aq[ks][3] = p[8 * SQ_P + 4];
    }

    // ---------------- GEMM1: B fragments straight from gmem ------------------
    // score col (within tile) block = w8; K row = kt*64 + w8 + gid
    {
        const float* pk = Kg + (size_t)(w8 + gid) * Dc + tig;
        float bk[2][16];
#pragma unroll
        for (int ks = 0; ks < 8; ks++) {
            bk[0][2 * ks]     = to_tf32(pk[ks * 8]);
            bk[0][2 * ks + 1] = to_tf32(pk[ks * 8 + 4]);
        }
        for (int kt = 0; kt < Sc / KT; kt++) {
            int cur = kt & 1;
            if (kt < 15) {
                const float* pn = pk + (size_t)(kt + 1) * KT * Dc;
#pragma unroll
                for (int ks = 0; ks < 8; ks++) {
                    bk[cur ^ 1][2 * ks]     = to_tf32(pn[ks * 8]);
                    bk[cur ^ 1][2 * ks + 1] = to_tf32(pn[ks * 8 + 4]);
                }
            }
            float c[4] = {0.f, 0.f, 0.f, 0.f};
#pragma unroll
            for (int ks = 0; ks < 8; ks++)
                mma8(c, aq[ks][0], aq[ks][1], aq[ks][2], aq[ks][3],
                     bk[cur][2 * ks], bk[cur][2 * ks + 1]);

            int col = kt * KT + w8 + tig * 2;
            float* p  = sS + gid * SS_P + col;
            float* p2 = p + 8 * SS_P;
            p[0]  = c[0]; p[1]  = c[1];
            p2[0] = c[2]; p2[1] = c[3];
        }
    }
    __syncthreads();

    // ---------------- softmax + post-softmax mask + attn write ---------------
#pragma unroll
    for (int rr = 0; rr < 2; rr++) {      // each warp owns 2 rows
        int row = warp * 2 + rr;
        float* srow = sS + row * SS_P;
        float4* srow4 = reinterpret_cast<float4*>(srow);

        float mx = -3.0e38f;
#pragma unroll
        for (int i = 0; i < 8; i++) {
            float4 v = srow4[lane + i * 32];
            mx = fmaxf(mx, fmaxf(fmaxf(v.x, v.y), fmaxf(v.z, v.w)));
        }
#pragma unroll
        for (int o = 16; o > 0; o >>= 1)
            mx = fmaxf(mx, __shfl_xor_sync(0xffffffffu, mx, o));

        float sum = 0.f;
        float4 e[8];
#pragma unroll
        for (int i = 0; i < 8; i++) {
            float4 v = srow4[lane + i * 32];
            v.x = __expf(v.x - mx); v.y = __expf(v.y - mx);
            v.z = __expf(v.z - mx); v.w = __expf(v.w - mx);
            e[i] = v;
            sum += (v.x + v.y) + (v.z + v.w);
        }
#pragma unroll
        for (int o = 16; o > 0; o >>= 1)
            sum += __shfl_xor_sync(0xffffffffu, sum, o);
        float inv = 1.0f / sum;

        const int4* mrow = reinterpret_cast<const int4*>(Mg + (size_t)row * Sc);
        float4* arow = reinterpret_cast<float4*>(outA + (size_t)row * Sc);
#pragma unroll
        for (int i = 0; i < 8; i++) {
            int idx = lane + i * 32;
            int4 m = mrow[idx];
            float4 w;
            w.x = m.x ? e[i].x * inv : -100000.0f;
            w.y = m.y ? e[i].y * inv : -100000.0f;
            w.z = m.z ? e[i].z * inv : -100000.0f;
            w.w = m.w ? e[i].w * inv : -100000.0f;
            __stcs(&arow[idx], w);                 // exact fp32 attn, streaming
            float4 t;                              // tf32 copy for GEMM2
            t.x = to_tf32(w.x); t.y = to_tf32(w.y);
            t.z = to_tf32(w.z); t.w = to_tf32(w.w);
            srow4[idx] = t;
        }
    }
    __syncthreads();

    // ---------------- GEMM2: k-split across warps, V direct from gmem --------
    // Warp owns k-tiles {2*warp, 2*warp+1}; computes full 16x64 partial.
    float c2[8][4];
#pragma unroll
    for (int nb = 0; nb < 8; nb++) {
        c2[nb][0] = 0.f; c2[nb][1] = 0.f; c2[nb][2] = 0.f; c2[nb][3] = 0.f;
    }
    {
        const int wt0 = warp * 2;
        // V element (step, nb, j): Vg[(wt0*64 + step*8 + tig + j*4)*64 + nb*8 + gid]
        const float* pv = Vg + (size_t)wt0 * KT * Dc + (size_t)tig * Dc + gid;
        const float* pa = sS + gid * SS_P + wt0 * KT + tig;

        float bv[2][16];
#pragma unroll
        for (int nb = 0; nb < 8; nb++) {
            bv[0][2 * nb]     = to_tf32(pv[nb * 8]);
            bv[0][2 * nb + 1] = to_tf32(pv[256 + nb * 8]);
        }
        for (int step = 0; step < 16; step++) {
            int cur = step & 1;
            if (step < 15) {
                const float* pn = pv + (size_t)(step + 1) * 8 * Dc;
#pragma unroll
                for (int nb = 0; nb < 8; nb++) {
                    bv[cur ^ 1][2 * nb]     = to_tf32(pn[nb * 8]);
                    bv[cur ^ 1][2 * nb + 1] = to_tf32(pn[256 + nb * 8]);
                }
            }
            const float* ap = pa + step * 8;
            float a0 = ap[0];
            float a1 = ap[8 * SS_P];
            float a2 = ap[4];
            float a3 = ap[8 * SS_P + 4];
#pragma unroll
            for (int nb = 0; nb < 8; nb++)
                mma8(c2[nb], a0, a1, a2, a3,
                     bv[cur][2 * nb], bv[cur][2 * nb + 1]);
        }
    }
    __syncthreads();      // all warps done reading sS attn

    // ---------------- cross-warp reduction of partials (reuse sS) ------------
    {
        float* sP = sS;   // [8 warps][16 rows][PP]
#pragma unroll
        for (int nb = 0; nb < 8; nb++) {
            float2* p0 = reinterpret_cast<float2*>(
                sP + warp * (TQ * PP) + gid * PP + nb * 8 + tig * 2);
            float2* p1 = reinterpret_cast<float2*>(
                sP + warp * (TQ * PP) + (gid + 8) * PP + nb * 8 + tig * 2);
            *p0 = make_float2(c2[nb][0], c2[nb][1]);
            *p1 = make_float2(c2[nb][2], c2[nb][3]);
        }
        __syncthreads();

        int r  = tid >> 4;          // 0..15
        int cc = (tid & 15) * 4;    // 0..60
        float4 acc = make_float4(0.f, 0.f, 0.f, 0.f);
#pragma unroll
        for (int w = 0; w < 8; w++) {
            float4 v = *reinterpret_cast<const float4*>(
                sP + w * (TQ * PP) + r * PP + cc);
            acc.x += v.x; acc.y += v.y; acc.z += v.z; acc.w += v.w;
        }
        *reinterpret_cast<float4*>(outO + r * Dc + cc) = acc;
    }
}

extern "C" void kernel_launch(void* const* d_in, const int* in_sizes, int n_in,
                              void* d_out, int out_size)
{
    (void)in_sizes; (void)n_in; (void)out_size;
    const float* Q = (const float*)d_in[0];
    const float* K = (const float*)d_in[1];
    const float* V = (const float*)d_in[2];
    const int*   M = (const int*)d_in[3];
    float* out = (float*)d_out;

    cudaFuncSetAttribute(attn_tf32_kernel,
                         cudaFuncAttributeMaxDynamicSharedMemorySize,
                         SMEM_FLOATS * (int)sizeof(float));
    dim3 grid(Sc / TQ, BH);
    attn_tf32_kernel<<<grid, NT, SMEM_FLOATS * sizeof(float)>>>(Q, K, V, M, out);
}